// round 1
// baseline (speedup 1.0000x reference)
#include <cuda_runtime.h>
#include <cstdint>

#define NUM_A 8
#define EDIM 128
#define OUTSTRIDE (NUM_A * EDIM)   // 1024 floats per batch row of edge/out
#define KC 32                      // K elements per pipeline chunk
#define NCHUNK 8                   // total K = 256 (128 img + 128 edge)
#define MTILE 128
#define THREADS 256
#define STAGE_BYTES (2 * EDIM * KC * 4)   // A tile (16KB) + B tile (16KB) = 32KB

// Precomputed fused weights (tf32-rounded) and bias-through-projection.
__device__ float g_P1T[NUM_A * EDIM * EDIM];   // [a][j][k] = sum_i W[i,k]   * proj[a,i,j]
__device__ float g_P2T[NUM_A * EDIM * EDIM];   // [a][j][k] = sum_i W[i,E+k] * proj[a,i,j]
__device__ float g_cvec[NUM_A * EDIM];         // [a][j]    = sum_i b[i]     * proj[a,i,j]

__device__ __forceinline__ uint32_t swz(uint32_t x) { return x ^ ((x >> 3) & 0x70u); }

__device__ __forceinline__ void cp_async16(uint32_t dst, const void* src) {
    asm volatile("cp.async.cg.shared.global [%0], [%1], 16;" :: "r"(dst), "l"(src));
}
__device__ __forceinline__ void cp_commit() { asm volatile("cp.async.commit_group;"); }
template <int N> __device__ __forceinline__ void cp_wait() {
    asm volatile("cp.async.wait_group %0;" :: "n"(N));
}

__device__ __forceinline__ void ldsm_x4(uint32_t& r0, uint32_t& r1, uint32_t& r2, uint32_t& r3,
                                        uint32_t addr) {
    asm volatile("ldmatrix.sync.aligned.m8n8.x4.shared.b16 {%0,%1,%2,%3}, [%4];"
                 : "=r"(r0), "=r"(r1), "=r"(r2), "=r"(r3) : "r"(addr));
}
__device__ __forceinline__ uint32_t to_tf32(uint32_t x) {
    uint32_t y;
    asm("cvt.rna.tf32.f32 %0, %1;" : "=r"(y) : "f"(__uint_as_float(x)));
    return y;
}
__device__ __forceinline__ void mma_tf32(float* c, const uint32_t* a, uint32_t b0, uint32_t b1) {
    asm volatile("mma.sync.aligned.m16n8k8.row.col.f32.tf32.tf32.f32 "
                 "{%0,%1,%2,%3},{%4,%5,%6,%7},{%8,%9},{%0,%1,%2,%3};"
                 : "+f"(c[0]), "+f"(c[1]), "+f"(c[2]), "+f"(c[3])
                 : "r"(a[0]), "r"(a[1]), "r"(a[2]), "r"(a[3]), "r"(b0), "r"(b1));
}

// ---------------------------------------------------------------------------
// Precompute: P1T/P2T (stored j-major = n-major, tf32-rounded) and cvec.
// grid (A, E) blocks x E threads (thread = k). 67 MFLOP total, negligible.
// ---------------------------------------------------------------------------
__global__ void precompute_kernel(const float* __restrict__ W, const float* __restrict__ bvec,
                                  const float* __restrict__ proj) {
    const int a = blockIdx.x;
    const int j = blockIdx.y;
    const int k = threadIdx.x;
    const float* pa = proj + ((size_t)a * EDIM) * EDIM + j;   // proj[a][i][j], stride E
    float acc1 = 0.f, acc2 = 0.f, accC = 0.f;
#pragma unroll 4
    for (int i = 0; i < EDIM; i++) {
        float p = __ldg(pa + (size_t)i * EDIM);
        acc1 = fmaf(__ldg(W + i * 2 * EDIM + k), p, acc1);
        acc2 = fmaf(__ldg(W + i * 2 * EDIM + EDIM + k), p, acc2);
        accC = fmaf(__ldg(bvec + i), p, accC);
    }
    size_t o = ((size_t)a * EDIM + j) * EDIM + k;
    g_P1T[o] = __uint_as_float(to_tf32(__float_as_uint(acc1)));
    g_P2T[o] = __uint_as_float(to_tf32(__float_as_uint(acc2)));
    if (k == 0) g_cvec[a * EDIM + j] = accC;
}

// ---------------------------------------------------------------------------
// Main fused GEMM: per CTA one (a, m-tile of 128 rows), C[128,128] fp32 accum.
// A = [img(K 0..127) | edge_a(K 128..255)] row-major; B = PnT[a] n-major in smem.
// tf32 mma.sync m16n8k8, cp.async double-buffered K pipeline, SW128 swizzle.
// ---------------------------------------------------------------------------
__global__ __launch_bounds__(THREADS, 1) void gnn_kernel(const float* __restrict__ img,
                                                         const float* __restrict__ edge,
                                                         float* __restrict__ out) {
    extern __shared__ float smem[];
    const uint32_t smem_b = (uint32_t)__cvta_generic_to_shared(smem);
    const int a = blockIdx.x;
    const int mbase = blockIdx.y * MTILE;
    const int tid = threadIdx.x;
    const int lane = tid & 31;
    const int warp = tid >> 5;
    const int m0 = (warp & 3) * 32;    // warp row base within CTA tile
    const int n0 = (warp >> 2) * 64;   // warp col base within CTA tile

    float acc[2][8][4];
#pragma unroll
    for (int mt = 0; mt < 2; mt++)
#pragma unroll
        for (int nt = 0; nt < 8; nt++)
#pragma unroll
            for (int v = 0; v < 4; v++) acc[mt][nt][v] = 0.f;

    auto load_chunk = [&](int kc, int s) {
        const uint32_t abase = smem_b + s * STAGE_BYTES;
        const uint32_t bbase = abase + EDIM * KC * 4;
        const float* srcAbase;
        size_t strideA;
        if (kc < 4) { srcAbase = img + (size_t)mbase * EDIM + kc * KC;                 strideA = EDIM; }
        else        { srcAbase = edge + (size_t)mbase * OUTSTRIDE + a * EDIM + (kc - 4) * KC; strideA = OUTSTRIDE; }
        const float* PT = (kc < 4) ? g_P1T : g_P2T;
        const float* srcBbase = PT + ((size_t)a * EDIM) * EDIM + (kc & 3) * KC;
#pragma unroll
        for (int q = 0; q < 4; q++) {
            int id = tid + q * THREADS;   // 0..1023
            int row = id >> 3;
            int c4 = id & 7;
            cp_async16(abase + swz((uint32_t)(row * 128 + c4 * 16)),
                       srcAbase + (size_t)row * strideA + c4 * 4);
        }
#pragma unroll
        for (int q = 0; q < 4; q++) {
            int id = tid + q * THREADS;
            int row = id >> 3;            // = j
            int c4 = id & 7;
            cp_async16(bbase + swz((uint32_t)(row * 128 + c4 * 16)),
                       srcBbase + (size_t)row * EDIM + c4 * 4);
        }
        cp_commit();
    };

    auto compute_chunk = [&](int s) {
        const uint32_t abase = smem_b + s * STAGE_BYTES;
        const uint32_t bbase = abase + EDIM * KC * 4;
#pragma unroll
        for (int ks = 0; ks < 4; ks++) {   // 4 k8 steps per 32-wide chunk
            uint32_t afr[2][4];
#pragma unroll
            for (int mt = 0; mt < 2; mt++) {
                int rowA = m0 + mt * 16 + (lane & 7) + (lane & 8);
                uint32_t kb = (uint32_t)(ks * 32 + (lane & 16));
                ldsm_x4(afr[mt][0], afr[mt][1], afr[mt][2], afr[mt][3],
                        abase + rowA * 128 + (kb ^ (uint32_t)((rowA & 7) << 4)));
            }
#pragma unroll
            for (int mt = 0; mt < 2; mt++)
#pragma unroll
                for (int v = 0; v < 4; v++) afr[mt][v] = to_tf32(afr[mt][v]);
            uint32_t bfr[4][4];
#pragma unroll
            for (int nt2 = 0; nt2 < 4; nt2++) {
                int rowB = n0 + nt2 * 16 + (lane & 7) + ((lane & 16) >> 1);
                uint32_t kb = (uint32_t)(ks * 32 + ((lane & 8) << 1));
                ldsm_x4(bfr[nt2][0], bfr[nt2][1], bfr[nt2][2], bfr[nt2][3],
                        bbase + rowB * 128 + (kb ^ (uint32_t)((rowB & 7) << 4)));
            }
#pragma unroll
            for (int mt = 0; mt < 2; mt++)
#pragma unroll
                for (int nt2 = 0; nt2 < 4; nt2++) {
                    mma_tf32(acc[mt][nt2 * 2],     afr[mt], bfr[nt2][0], bfr[nt2][1]);
                    mma_tf32(acc[mt][nt2 * 2 + 1], afr[mt], bfr[nt2][2], bfr[nt2][3]);
                }
        }
    };

    load_chunk(0, 0);
    load_chunk(1, 1);
    for (int kc = 0; kc < NCHUNK; kc++) {
        if (kc < NCHUNK - 2) { cp_wait<1>(); } else { cp_wait<0>(); }
        __syncthreads();
        compute_chunk(kc & 1);
        __syncthreads();
        if (kc < NCHUNK - 2) load_chunk(kc + 2, kc & 1);
    }

    // Epilogue: add bias-through-projection, store float2 pairs (32B sectors, fully used).
    const float* cv = g_cvec + a * EDIM;
#pragma unroll
    for (int mt = 0; mt < 2; mt++) {
        int r0 = mbase + m0 + mt * 16 + (lane >> 2);
#pragma unroll
        for (int nt = 0; nt < 8; nt++) {
            int col = n0 + (nt >> 1) * 16 + (nt & 1) * 8 + (lane & 3) * 2;
            float b0 = __ldg(cv + col);
            float b1 = __ldg(cv + col + 1);
            float2 v0 = make_float2(acc[mt][nt][0] + b0, acc[mt][nt][1] + b1);
            float2 v1 = make_float2(acc[mt][nt][2] + b0, acc[mt][nt][3] + b1);
            size_t base0 = (size_t)r0 * OUTSTRIDE + a * EDIM + col;
            size_t base1 = (size_t)(r0 + 8) * OUTSTRIDE + a * EDIM + col;
            *reinterpret_cast<float2*>(out + base0) = v0;
            *reinterpret_cast<float2*>(out + base1) = v1;
        }
    }
}

extern "C" void kernel_launch(void* const* d_in, const int* in_sizes, int n_in,
                              void* d_out, int out_size) {
    const float* img  = (const float*)d_in[0];   // [B, E]
    const float* edge = (const float*)d_in[1];   // [B, A, E]
    const float* W    = (const float*)d_in[2];   // [E, 2E]
    const float* bvec = (const float*)d_in[3];   // [E]
    const float* proj = (const float*)d_in[4];   // [A, E, E]
    const int Bn = in_sizes[0] / EDIM;

    precompute_kernel<<<dim3(NUM_A, EDIM), EDIM>>>(W, bvec, proj);

    cudaFuncSetAttribute(gnn_kernel, cudaFuncAttributeMaxDynamicSharedMemorySize,
                         2 * STAGE_BYTES);
    // blockIdx.x = a (fast dim) so the 8 a-CTAs of one m-tile run adjacently:
    // img tile and the 512KB contiguous edge row block get full L2 reuse.
    gnn_kernel<<<dim3(NUM_A, Bn / MTILE), THREADS, 2 * STAGE_BYTES>>>(
        img, edge, (float*)d_out);
}

// round 2
// speedup vs baseline: 1.3300x; 1.3300x over previous
#include <cuda_runtime.h>
#include <cstdint>

#define NUM_A 8
#define EDIM 128
#define OUTSTRIDE (NUM_A * EDIM)   // 1024 floats per batch row of edge/out
#define KC 32                      // K elements per pipeline chunk
#define NCHUNK 8                   // total K = 256 (128 img + 128 edge)
#define MTILE 128
#define THREADS 256
#define STAGE_BYTES (2 * EDIM * KC * 4)   // A tile (16KB) + B tile (16KB) = 32KB

// Precomputed fused weights (tf32-rounded) and bias-through-projection.
__device__ float g_P1T[NUM_A * EDIM * EDIM];   // [a][j][k] = sum_i W[i,k]   * proj[a,i,j]
__device__ float g_P2T[NUM_A * EDIM * EDIM];   // [a][j][k] = sum_i W[i,E+k] * proj[a,i,j]
__device__ float g_cvec[NUM_A * EDIM];         // [a][j]    = sum_i b[i]     * proj[a,i,j]

__device__ __forceinline__ uint32_t swz(uint32_t x) { return x ^ ((x >> 3) & 0x70u); }

__device__ __forceinline__ void cp_async16(uint32_t dst, const void* src) {
    asm volatile("cp.async.cg.shared.global [%0], [%1], 16;" :: "r"(dst), "l"(src));
}
__device__ __forceinline__ void cp_commit() { asm volatile("cp.async.commit_group;"); }
template <int N> __device__ __forceinline__ void cp_wait() {
    asm volatile("cp.async.wait_group %0;" :: "n"(N));
}

__device__ __forceinline__ void ldsm_x4(uint32_t& r0, uint32_t& r1, uint32_t& r2, uint32_t& r3,
                                        uint32_t addr) {
    asm volatile("ldmatrix.sync.aligned.m8n8.x4.shared.b16 {%0,%1,%2,%3}, [%4];"
                 : "=r"(r0), "=r"(r1), "=r"(r2), "=r"(r3) : "r"(addr));
}
__device__ __forceinline__ uint32_t to_tf32(uint32_t x) {
    uint32_t y;
    asm("cvt.rna.tf32.f32 %0, %1;" : "=r"(y) : "f"(__uint_as_float(x)));
    return y;
}
__device__ __forceinline__ void mma_tf32(float* c, const uint32_t* a, uint32_t b0, uint32_t b1) {
    asm volatile("mma.sync.aligned.m16n8k8.row.col.f32.tf32.tf32.f32 "
                 "{%0,%1,%2,%3},{%4,%5,%6,%7},{%8,%9},{%0,%1,%2,%3};"
                 : "+f"(c[0]), "+f"(c[1]), "+f"(c[2]), "+f"(c[3])
                 : "r"(a[0]), "r"(a[1]), "r"(a[2]), "r"(a[3]), "r"(b0), "r"(b1));
}

// ---------------------------------------------------------------------------
// Precompute: P1T/P2T (stored j-major = n-major, tf32-rounded) and cvec.
// grid (A, E) blocks x E threads (thread = k). 67 MFLOP total, negligible.
// ---------------------------------------------------------------------------
__global__ void precompute_kernel(const float* __restrict__ W, const float* __restrict__ bvec,
                                  const float* __restrict__ proj) {
    const int a = blockIdx.x;
    const int j = blockIdx.y;
    const int k = threadIdx.x;
    const float* pa = proj + ((size_t)a * EDIM) * EDIM + j;   // proj[a][i][j], stride E
    float acc1 = 0.f, acc2 = 0.f, accC = 0.f;
#pragma unroll 8
    for (int i = 0; i < EDIM; i++) {
        float p = __ldg(pa + (size_t)i * EDIM);
        acc1 = fmaf(__ldg(W + i * 2 * EDIM + k), p, acc1);
        acc2 = fmaf(__ldg(W + i * 2 * EDIM + EDIM + k), p, acc2);
        accC = fmaf(__ldg(bvec + i), p, accC);
    }
    size_t o = ((size_t)a * EDIM + j) * EDIM + k;
    g_P1T[o] = __uint_as_float(to_tf32(__float_as_uint(acc1)));
    g_P2T[o] = __uint_as_float(to_tf32(__float_as_uint(acc2)));
    if (k == 0) g_cvec[a * EDIM + j] = accC;
}

// ---------------------------------------------------------------------------
// Main fused GEMM: per CTA one (a, m-tile of 128 rows), C[128,128] fp32 accum.
// A = [img(K 0..127) | edge_a(K 128..255)] row-major; B = PnT[a] n-major in smem.
// tf32 mma.sync m16n8k8, cp.async double-buffered K pipeline, SW128 swizzle.
// 2 CTAs/SM (launch_bounds minBlocks=2) to hide ldmatrix/mma latency + barriers.
// ---------------------------------------------------------------------------
__global__ __launch_bounds__(THREADS, 2) void gnn_kernel(const float* __restrict__ img,
                                                         const float* __restrict__ edge,
                                                         float* __restrict__ out) {
    extern __shared__ float smem[];
    const uint32_t smem_b = (uint32_t)__cvta_generic_to_shared(smem);
    const int a = blockIdx.x;
    const int mbase = blockIdx.y * MTILE;
    const int tid = threadIdx.x;
    const int lane = tid & 31;
    const int warp = tid >> 5;
    const int m0 = (warp & 3) * 32;    // warp row base within CTA tile
    const int n0 = (warp >> 2) * 64;   // warp col base within CTA tile

    float acc[2][8][4];
#pragma unroll
    for (int mt = 0; mt < 2; mt++)
#pragma unroll
        for (int nt = 0; nt < 8; nt++)
#pragma unroll
            for (int v = 0; v < 4; v++) acc[mt][nt][v] = 0.f;

    auto load_chunk = [&](int kc, int s) {
        const uint32_t abase = smem_b + s * STAGE_BYTES;
        const uint32_t bbase = abase + EDIM * KC * 4;
        const float* srcAbase;
        size_t strideA;
        if (kc < 4) { srcAbase = img + (size_t)mbase * EDIM + kc * KC;                 strideA = EDIM; }
        else        { srcAbase = edge + (size_t)mbase * OUTSTRIDE + a * EDIM + (kc - 4) * KC; strideA = OUTSTRIDE; }
        const float* PT = (kc < 4) ? g_P1T : g_P2T;
        const float* srcBbase = PT + ((size_t)a * EDIM) * EDIM + (kc & 3) * KC;
#pragma unroll
        for (int q = 0; q < 4; q++) {
            int id = tid + q * THREADS;   // 0..1023
            int row = id >> 3;
            int c4 = id & 7;
            cp_async16(abase + swz((uint32_t)(row * 128 + c4 * 16)),
                       srcAbase + (size_t)row * strideA + c4 * 4);
        }
#pragma unroll
        for (int q = 0; q < 4; q++) {
            int id = tid + q * THREADS;
            int row = id >> 3;            // = j
            int c4 = id & 7;
            cp_async16(bbase + swz((uint32_t)(row * 128 + c4 * 16)),
                       srcBbase + (size_t)row * EDIM + c4 * 4);
        }
        cp_commit();
    };

    auto compute_chunk = [&](int s) {
        const uint32_t abase = smem_b + s * STAGE_BYTES;
        const uint32_t bbase = abase + EDIM * KC * 4;
#pragma unroll
        for (int ks = 0; ks < 4; ks++) {   // 4 k8 steps per 32-wide chunk
            uint32_t afr[2][4];
#pragma unroll
            for (int mt = 0; mt < 2; mt++) {
                int rowA = m0 + mt * 16 + (lane & 7) + (lane & 8);
                uint32_t kb = (uint32_t)(ks * 32 + (lane & 16));
                ldsm_x4(afr[mt][0], afr[mt][1], afr[mt][2], afr[mt][3],
                        abase + rowA * 128 + (kb ^ (uint32_t)((rowA & 7) << 4)));
            }
#pragma unroll
            for (int mt = 0; mt < 2; mt++)
#pragma unroll
                for (int v = 0; v < 4; v++) afr[mt][v] = to_tf32(afr[mt][v]);
            uint32_t bfr[4][4];
#pragma unroll
            for (int nt2 = 0; nt2 < 4; nt2++) {
                int rowB = n0 + nt2 * 16 + (lane & 7) + ((lane & 16) >> 1);
                uint32_t kb = (uint32_t)(ks * 32 + ((lane & 8) << 1));
                ldsm_x4(bfr[nt2][0], bfr[nt2][1], bfr[nt2][2], bfr[nt2][3],
                        bbase + rowB * 128 + (kb ^ (uint32_t)((rowB & 7) << 4)));
            }
#pragma unroll
            for (int mt = 0; mt < 2; mt++)
#pragma unroll
                for (int nt2 = 0; nt2 < 4; nt2++) {
                    mma_tf32(acc[mt][nt2 * 2],     afr[mt], bfr[nt2][0], bfr[nt2][1]);
                    mma_tf32(acc[mt][nt2 * 2 + 1], afr[mt], bfr[nt2][2], bfr[nt2][3]);
                }
        }
    };

    load_chunk(0, 0);
    load_chunk(1, 1);
    for (int kc = 0; kc < NCHUNK; kc++) {
        if (kc < NCHUNK - 2) { cp_wait<1>(); } else { cp_wait<0>(); }
        __syncthreads();
        compute_chunk(kc & 1);
        __syncthreads();
        if (kc < NCHUNK - 2) load_chunk(kc + 2, kc & 1);
    }

    // Epilogue: add bias-through-projection, store float2 pairs (32B sectors, fully used).
    const float* cv = g_cvec + a * EDIM;
#pragma unroll
    for (int mt = 0; mt < 2; mt++) {
        int r0 = mbase + m0 + mt * 16 + (lane >> 2);
#pragma unroll
        for (int nt = 0; nt < 8; nt++) {
            int col = n0 + (nt >> 1) * 16 + (nt & 1) * 8 + (lane & 3) * 2;
            float b0 = __ldg(cv + col);
            float b1 = __ldg(cv + col + 1);
            float2 v0 = make_float2(acc[mt][nt][0] + b0, acc[mt][nt][1] + b1);
            float2 v1 = make_float2(acc[mt][nt][2] + b0, acc[mt][nt][3] + b1);
            size_t base0 = (size_t)r0 * OUTSTRIDE + a * EDIM + col;
            size_t base1 = (size_t)(r0 + 8) * OUTSTRIDE + a * EDIM + col;
            *reinterpret_cast<float2*>(out + base0) = v0;
            *reinterpret_cast<float2*>(out + base1) = v1;
        }
    }
}

extern "C" void kernel_launch(void* const* d_in, const int* in_sizes, int n_in,
                              void* d_out, int out_size) {
    const float* img  = (const float*)d_in[0];   // [B, E]
    const float* edge = (const float*)d_in[1];   // [B, A, E]
    const float* W    = (const float*)d_in[2];   // [E, 2E]
    const float* bvec = (const float*)d_in[3];   // [E]
    const float* proj = (const float*)d_in[4];   // [A, E, E]
    const int Bn = in_sizes[0] / EDIM;

    precompute_kernel<<<dim3(NUM_A, EDIM), EDIM>>>(W, bvec, proj);

    cudaFuncSetAttribute(gnn_kernel, cudaFuncAttributeMaxDynamicSharedMemorySize,
                         2 * STAGE_BYTES);
    // blockIdx.x = a (fast dim) so the 8 a-CTAs of one m-tile run adjacently:
    // img tile and the 512KB contiguous edge row block get full L2 reuse.
    gnn_kernel<<<dim3(NUM_A, Bn / MTILE), THREADS, 2 * STAGE_BYTES>>>(
        img, edge, (float*)d_out);
}

// round 4
// speedup vs baseline: 1.3648x; 1.0262x over previous
#include <cuda_runtime.h>
#include <cstdint>

#define NUM_A 8
#define EDIM 128
#define OUTSTRIDE (NUM_A * EDIM)   // 1024 floats per batch row of edge/out
#define KC 32                      // K elements per pipeline chunk
#define NCHUNK 8                   // total K = 256 (128 img + 128 edge)
#define NSTAGE 3
#define MTILE 128
#define THREADS 256
#define STAGE_BYTES (2 * EDIM * KC * 4)   // A tile (16KB) + B tile (16KB) = 32KB

// Precomputed fused weights (tf32-rounded) and bias-through-projection.
__device__ float g_P1T[NUM_A * EDIM * EDIM];   // [a][j][k] = sum_i W[i,k]   * proj[a,i,j]
__device__ float g_P2T[NUM_A * EDIM * EDIM];   // [a][j][k] = sum_i W[i,E+k] * proj[a,i,j]
__device__ float g_cvec[NUM_A * EDIM];         // [a][j]    = sum_i b[i]     * proj[a,i,j]

__device__ __forceinline__ uint32_t swz(uint32_t x) { return x ^ ((x >> 3) & 0x70u); }

__device__ __forceinline__ void cp_async16(uint32_t dst, const void* src) {
    asm volatile("cp.async.cg.shared.global [%0], [%1], 16;" :: "r"(dst), "l"(src));
}
__device__ __forceinline__ void cp_commit() { asm volatile("cp.async.commit_group;"); }
template <int N> __device__ __forceinline__ void cp_wait() {
    asm volatile("cp.async.wait_group %0;" :: "n"(N));
}

__device__ __forceinline__ void ldsm_x4(uint32_t& r0, uint32_t& r1, uint32_t& r2, uint32_t& r3,
                                        uint32_t addr) {
    asm volatile("ldmatrix.sync.aligned.m8n8.x4.shared.b16 {%0,%1,%2,%3}, [%4];"
                 : "=r"(r0), "=r"(r1), "=r"(r2), "=r"(r3) : "r"(addr));
}
__device__ __forceinline__ uint32_t to_tf32(uint32_t x) {
    uint32_t y;
    asm("cvt.rna.tf32.f32 %0, %1;" : "=r"(y) : "f"(__uint_as_float(x)));
    return y;
}
__device__ __forceinline__ void mma_tf32(float* c, const uint32_t* a, uint32_t b0, uint32_t b1) {
    asm volatile("mma.sync.aligned.m16n8k8.row.col.f32.tf32.tf32.f32 "
                 "{%0,%1,%2,%3},{%4,%5,%6,%7},{%8,%9},{%0,%1,%2,%3};"
                 : "+f"(c[0]), "+f"(c[1]), "+f"(c[2]), "+f"(c[3])
                 : "r"(a[0]), "r"(a[1]), "r"(a[2]), "r"(a[3]), "r"(b0), "r"(b1));
}

// ---------------------------------------------------------------------------
// Precompute: P1T/P2T (stored j-major = n-major, tf32-rounded) and cvec.
// ---------------------------------------------------------------------------
__global__ void precompute_kernel(const float* __restrict__ W, const float* __restrict__ bvec,
                                  const float* __restrict__ proj) {
    const int a = blockIdx.x;
    const int j = blockIdx.y;
    const int k = threadIdx.x;
    const float* pa = proj + ((size_t)a * EDIM) * EDIM + j;   // proj[a][i][j], stride E
    float acc1 = 0.f, acc2 = 0.f, accC = 0.f;
#pragma unroll 8
    for (int i = 0; i < EDIM; i++) {
        float p = __ldg(pa + (size_t)i * EDIM);
        acc1 = fmaf(__ldg(W + i * 2 * EDIM + k), p, acc1);
        acc2 = fmaf(__ldg(W + i * 2 * EDIM + EDIM + k), p, acc2);
        accC = fmaf(__ldg(bvec + i), p, accC);
    }
    size_t o = ((size_t)a * EDIM + j) * EDIM + k;
    g_P1T[o] = __uint_as_float(to_tf32(__float_as_uint(acc1)));
    g_P2T[o] = __uint_as_float(to_tf32(__float_as_uint(acc2)));
    if (k == 0) g_cvec[a * EDIM + j] = accC;
}

// ---------------------------------------------------------------------------
// Main fused GEMM: per CTA one (a, m-tile of 128 rows), C[128,128] fp32 accum.
// tf32 mma.sync m16n8k8; 3-stage cp.async pipeline, loads issued 2 chunks
// ahead and BEFORE compute; ONE barrier per chunk. 2 CTAs/SM.
// ---------------------------------------------------------------------------
__global__ __launch_bounds__(THREADS, 2) void gnn_kernel(const float* __restrict__ img,
                                                         const float* __restrict__ edge,
                                                         float* __restrict__ out) {
    extern __shared__ float smem[];
    const uint32_t smem_b = (uint32_t)__cvta_generic_to_shared(smem);
    const int a = blockIdx.x;
    const int mbase = blockIdx.y * MTILE;
    const int tid = threadIdx.x;
    const int lane = tid & 31;
    const int warp = tid >> 5;
    const int m0 = (warp & 3) * 32;    // warp row base within CTA tile
    const int n0 = (warp >> 2) * 64;   // warp col base within CTA tile

    float acc[2][8][4];
#pragma unroll
    for (int mt = 0; mt < 2; mt++)
#pragma unroll
        for (int nt = 0; nt < 8; nt++)
#pragma unroll
            for (int v = 0; v < 4; v++) acc[mt][nt][v] = 0.f;

    auto load_chunk = [&](int kc, int s) {
        const uint32_t abase = smem_b + s * STAGE_BYTES;
        const uint32_t bbase = abase + EDIM * KC * 4;
        const float* srcAbase;
        size_t strideA;
        if (kc < 4) { srcAbase = img + (size_t)mbase * EDIM + kc * KC;                 strideA = EDIM; }
        else        { srcAbase = edge + (size_t)mbase * OUTSTRIDE + a * EDIM + (kc - 4) * KC; strideA = OUTSTRIDE; }
        const float* PT = (kc < 4) ? g_P1T : g_P2T;
        const float* srcBbase = PT + ((size_t)a * EDIM) * EDIM + (kc & 3) * KC;
#pragma unroll
        for (int q = 0; q < 4; q++) {
            int id = tid + q * THREADS;   // 0..1023
            int row = id >> 3;
            int c4 = id & 7;
            cp_async16(abase + swz((uint32_t)(row * 128 + c4 * 16)),
                       srcAbase + (size_t)row * strideA + c4 * 4);
        }
#pragma unroll
        for (int q = 0; q < 4; q++) {
            int id = tid + q * THREADS;
            int row = id >> 3;            // = j
            int c4 = id & 7;
            cp_async16(bbase + swz((uint32_t)(row * 128 + c4 * 16)),
                       srcBbase + (size_t)row * EDIM + c4 * 4);
        }
        cp_commit();
    };

    auto compute_chunk = [&](int s) {
        const uint32_t abase = smem_b + s * STAGE_BYTES;
        const uint32_t bbase = abase + EDIM * KC * 4;
#pragma unroll
        for (int ks = 0; ks < 4; ks++) {   // 4 k8 steps per 32-wide chunk
            uint32_t afr[2][4];
#pragma unroll
            for (int mt = 0; mt < 2; mt++) {
                int rowA = m0 + mt * 16 + (lane & 7) + (lane & 8);
                uint32_t kb = (uint32_t)(ks * 32 + (lane & 16));
                ldsm_x4(afr[mt][0], afr[mt][1], afr[mt][2], afr[mt][3],
                        abase + rowA * 128 + (kb ^ (uint32_t)((rowA & 7) << 4)));
            }
#pragma unroll
            for (int mt = 0; mt < 2; mt++)
#pragma unroll
                for (int v = 0; v < 4; v++) afr[mt][v] = to_tf32(afr[mt][v]);
            uint32_t bfr[4][4];
#pragma unroll
            for (int nt2 = 0; nt2 < 4; nt2++) {
                int rowB = n0 + nt2 * 16 + (lane & 7) + ((lane & 16) >> 1);
                uint32_t kb = (uint32_t)(ks * 32 + ((lane & 8) << 1));
                ldsm_x4(bfr[nt2][0], bfr[nt2][1], bfr[nt2][2], bfr[nt2][3],
                        bbase + rowB * 128 + (kb ^ (uint32_t)((rowB & 7) << 4)));
            }
#pragma unroll
            for (int mt = 0; mt < 2; mt++)
#pragma unroll
                for (int nt2 = 0; nt2 < 4; nt2++) {
                    mma_tf32(acc[mt][nt2 * 2],     afr[mt], bfr[nt2][0], bfr[nt2][1]);
                    mma_tf32(acc[mt][nt2 * 2 + 1], afr[mt], bfr[nt2][2], bfr[nt2][3]);
                }
        }
    };

    // 3-stage pipeline: preload chunks 0,1; each iteration waits for chunk kc,
    // barriers ONCE, issues load kc+2 (into the stage freed by compute kc-1,
    // proven reached by all warps via the barrier), then computes kc while
    // loads kc+1 and kc+2 are in flight.
    load_chunk(0, 0);
    load_chunk(1, 1);
#pragma unroll 1
    for (int kc = 0; kc < NCHUNK; kc++) {
        if (kc < NCHUNK - 1) { cp_wait<1>(); } else { cp_wait<0>(); }
        __syncthreads();
        if (kc + 2 < NCHUNK) load_chunk(kc + 2, (kc + 2) % NSTAGE);
        compute_chunk(kc % NSTAGE);
    }

    // Epilogue: add bias-through-projection, store float2 pairs.
    const float* cv = g_cvec + a * EDIM;
#pragma unroll
    for (int mt = 0; mt < 2; mt++) {
        int r0 = mbase + m0 + mt * 16 + (lane >> 2);
#pragma unroll
        for (int nt = 0; nt < 8; nt++) {
            int col = n0 + (nt >> 1) * 16 + (nt & 1) * 8 + (lane & 3) * 2;
            float b0 = __ldg(cv + col);
            float b1 = __ldg(cv + col + 1);
            float2 v0 = make_float2(acc[mt][nt][0] + b0, acc[mt][nt][1] + b1);
            float2 v1 = make_float2(acc[mt][nt][2] + b0, acc[mt][nt][3] + b1);
            size_t base0 = (size_t)r0 * OUTSTRIDE + a * EDIM + col;
            size_t base1 = (size_t)(r0 + 8) * OUTSTRIDE + a * EDIM + col;
            *reinterpret_cast<float2*>(out + base0) = v0;
            *reinterpret_cast<float2*>(out + base1) = v1;
        }
    }
}

extern "C" void kernel_launch(void* const* d_in, const int* in_sizes, int n_in,
                              void* d_out, int out_size) {
    const float* img  = (const float*)d_in[0];   // [B, E]
    const float* edge = (const float*)d_in[1];   // [B, A, E]
    const float* W    = (const float*)d_in[2];   // [E, 2E]
    const float* bvec = (const float*)d_in[3];   // [E]
    const float* proj = (const float*)d_in[4];   // [A, E, E]
    const int Bn = in_sizes[0] / EDIM;

    precompute_kernel<<<dim3(NUM_A, EDIM), EDIM>>>(W, bvec, proj);

    cudaFuncSetAttribute(gnn_kernel, cudaFuncAttributeMaxDynamicSharedMemorySize,
                         NSTAGE * STAGE_BYTES);
    // blockIdx.x = a (fast dim) so the 8 a-CTAs of one m-tile run adjacently:
    // img tile and the contiguous edge row block get full L2 reuse.
    gnn_kernel<<<dim3(NUM_A, Bn / MTILE), THREADS, NSTAGE * STAGE_BYTES>>>(
        img, edge, (float*)d_out);
}